// round 16
// baseline (speedup 1.0000x reference)
#include <cuda_runtime.h>
#include <cuda_fp16.h>
#include <cstdint>

// Problem constants (16 clips of 10 s @ 48 kHz)
#define N_SAMP  480000
#define NP1     480001          // envelope length per row
#define WIN     240             // 5 ms box filter
#define EPSW    (240.0f * 1e-6f)   // eps on raw window sums
#define LN2     0.6931471805599453

// Tiling: 256 threads, 16 d-elements each; window offset 240 = 15 thread slots.
#define NTHR    256
#define EPT     16
#define T_OUT   3840            // envelope outputs per tile
#define L_DV    (T_OUT + WIN - 1)   // 4079 valid d elements per tile
#define TILES_X 126             // tiles per row
#define GRID    592             // 148 SMs x 4 blocks: exactly one wave
#define MAXB    16

// Scratch (zero-initialized at load; reset by last block each run)
struct RowAcc { double s1, s2; int m; int pad[3]; };
__device__ RowAcc       g_acc[MAXB];
__device__ unsigned int g_count;

struct SMF {
    float   baseP[NTHR], baseT[NTHR];   // per-thread exclusive prefix bases
    __half2 h2P[NTHR * 9];              // local inclusive prefixes, idx 9t+k (CF)
    __half2 h2T[NTHR * 9];
    float   wsP[8], wsT[8];
    float   red1[8], red2[8], red3[8];
    double  fin[MAXB];
    int     flag;
};

struct TileRegs {                       // prefetched x data for one tile
    float eP[EPT], eT[EPT];
    float hP, hT;                       // per-thread halo x[j0-121+m0]
};

__device__ __forceinline__ bool tile_interior(int tx) {
    return (tx >= 1) && (tx <= TILES_X - 3);
}

// Issue all loads for tile tau (8x LDG.128 + 2 scalar); no dependent math.
__device__ __forceinline__ void load_tile(const float* __restrict__ yp,
                                          const float* __restrict__ yt,
                                          int tau, int m0, TileRegs& R)
{
    const int row = tau / TILES_X;
    const int tx  = tau - row * TILES_X;
    const float* xp = yp + (size_t)row * N_SAMP;
    const float* xt = yt + (size_t)row * N_SAMP;
    const int j0 = tx * T_OUT;
    if (tile_interior(tx)) {
        R.hP = xp[j0 - 121 + m0];               // same sectors as vector loads
        R.hT = xt[j0 - 121 + m0];
        const float4* p4 = reinterpret_cast<const float4*>(xp + (j0 - 120 + m0));
        const float4* q4 = reinterpret_cast<const float4*>(xt + (j0 - 120 + m0));
        float4 A0 = p4[0], A1 = p4[1], A2 = p4[2], A3 = p4[3];
        float4 B0 = q4[0], B1 = q4[1], B2 = q4[2], B3 = q4[3];
        R.eP[0]=A0.x; R.eP[1]=A0.y; R.eP[2]=A0.z; R.eP[3]=A0.w;
        R.eP[4]=A1.x; R.eP[5]=A1.y; R.eP[6]=A1.z; R.eP[7]=A1.w;
        R.eP[8]=A2.x; R.eP[9]=A2.y; R.eP[10]=A2.z; R.eP[11]=A2.w;
        R.eP[12]=A3.x; R.eP[13]=A3.y; R.eP[14]=A3.z; R.eP[15]=A3.w;
        R.eT[0]=B0.x; R.eT[1]=B0.y; R.eT[2]=B0.z; R.eT[3]=B0.w;
        R.eT[4]=B1.x; R.eT[5]=B1.y; R.eT[6]=B1.z; R.eT[7]=B1.w;
        R.eT[8]=B2.x; R.eT[9]=B2.y; R.eT[10]=B2.z; R.eT[11]=B2.w;
        R.eT[12]=B3.x; R.eT[13]=B3.y; R.eT[14]=B3.z; R.eT[15]=B3.w;
    } else {
        int i0 = j0 - 121 + m0;
        bool v0 = (i0 >= 0) && (i0 < N_SAMP);
        R.hP = v0 ? xp[i0] : 0.f;
        R.hT = v0 ? xt[i0] : 0.f;
        #pragma unroll
        for (int c = 0; c < EPT; c++) {
            int i = j0 - 120 + m0 + c;
            bool v = (i >= 0) && (i < N_SAMP);
            R.eP[c] = v ? xp[i] : 0.f;
            R.eT[c] = v ? xt[i] : 0.f;
        }
    }
}

// Consume tile regs: pack half2 local inclusive prefixes to smem, return totals.
__device__ __forceinline__ void diffs_consume(const TileRegs& R, bool interior,
                                              int j0, int m0,
                                              __half2* __restrict__ rp,
                                              __half2* __restrict__ rt,
                                              float& sP, float& sT)
{
    float pP = R.hP, pT = R.hT;
    sP = 0.f; sT = 0.f;
    if (interior) {
        #pragma unroll
        for (int k = 0; k < 8; k++) {
            float aP = sP + fabsf(R.eP[2*k]   - pP);
            float bP = aP + fabsf(R.eP[2*k+1] - R.eP[2*k]);
            rp[k] = __floats2half2_rn(aP, bP);
            pP = R.eP[2*k+1]; sP = bP;
            float aT = sT + fabsf(R.eT[2*k]   - pT);
            float bT = aT + fabsf(R.eT[2*k+1] - R.eT[2*k]);
            rt[k] = __floats2half2_rn(aT, bT);
            pT = R.eT[2*k+1]; sT = bT;
        }
    } else {
        #pragma unroll
        for (int k = 0; k < 8; k++) {
            float aa[2], bb[2];
            #pragma unroll
            for (int h = 0; h < 2; h++) {
                int c = 2*k + h;
                int i = j0 - 120 + m0 + c;       // x index == d index
                bool ok = (i >= 1) && (i < N_SAMP) && (m0 + c < L_DV);
                sP += ok ? fabsf(R.eP[c] - pP) : 0.f; pP = R.eP[c];
                sT += ok ? fabsf(R.eT[c] - pT) : 0.f; pT = R.eT[c];
                aa[h] = sP; bb[h] = sT;
            }
            rp[k] = __floats2half2_rn(aa[0], aa[1]);
            rt[k] = __floats2half2_rn(bb[0], bb[1]);
        }
    }
}

__global__ __launch_bounds__(NTHR, 4)
void k_fused(const float* __restrict__ y_pred, const float* __restrict__ y_true,
             float* __restrict__ out, int B, int n_tiles, double invcnt)
{
    __shared__ SMF sm;
    const int t = threadIdx.x, lane = t & 31, wid = t >> 5;
    const int m0 = t * EPT;

    TileRegs R;
    int tau = blockIdx.x;
    if (tau < n_tiles) load_tile(y_pred, y_true, tau, m0, R);

    while (tau < n_tiles) {
        const int row = tau / TILES_X;
        const int tx  = tau - row * TILES_X;
        const int j0  = tx * T_OUT;
        const bool interior = tile_interior(tx);

        float sP, sT;
        diffs_consume(R, interior, j0, m0, &sm.h2P[9 * t], &sm.h2T[9 * t], sP, sT);

        // ---- Prefetch next tile (loads in flight across scan/env/reduce) ----
        const int ntau = tau + GRID;
        if (ntau < n_tiles) load_tile(y_pred, y_true, ntau, m0, R);

        // ---- Interleaved warp scan of thread totals ----
        float vP = sP, vT = sT;
        #pragma unroll
        for (int off = 1; off < 32; off <<= 1) {
            float uP = __shfl_up_sync(0xffffffffu, vP, off);
            float uT = __shfl_up_sync(0xffffffffu, vT, off);
            if (lane >= off) { vP += uP; vT += uT; }
        }
        if (lane == 31) { sm.wsP[wid] = vP; sm.wsT[wid] = vT; }
        __syncthreads();

        float baseP = vP - sP, baseT = vT - sT;
        #pragma unroll
        for (int w = 0; w < 7; w++)
            if (w < wid) { baseP += sm.wsP[w]; baseT += sm.wsT[w]; }
        sm.baseP[t] = baseP;
        sm.baseT[t] = baseT;
        __syncthreads();

        // ---- Env + loss on the fly: S = (bN-bO) + (runN-runO) ----
        float s1 = 0.f, s2 = 0.f, mx = 0.f;
        if (t < T_OUT / EPT) {                       // t < 240
            const float DBP = sm.baseP[t + 15] - baseP;
            const float DBT = sm.baseT[t + 15] - baseT;
            const __half2* qp = &sm.h2P[9 * (t + 15)];
            const __half2* op = &sm.h2P[9 * t];
            const __half2* qt = &sm.h2T[9 * (t + 15)];
            const __half2* ot = &sm.h2T[9 * t];
            if (interior || (j0 + m0 < NP1)) {       // c = 0
                float df = fabsf(__log2f(DBP + EPSW) - __log2f(DBT + EPSW));
                s1 += df; s2 += df * DBT; mx = fmaxf(mx, DBT);
            }
            #pragma unroll
            for (int k = 0; k < 8; k++) {
                float2 fp = __half22float2(__hsub2(qp[k], op[k]));
                float2 ft = __half22float2(__hsub2(qt[k], ot[k]));
                {
                    int c = 2 * k + 1;
                    if (interior || (j0 + m0 + c < NP1)) {
                        float Sp = DBP + fp.x, St = DBT + ft.x;
                        float df = fabsf(__log2f(Sp + EPSW) - __log2f(St + EPSW));
                        s1 += df; s2 += df * St; mx = fmaxf(mx, St);
                    }
                }
                if (k < 7) {
                    int c = 2 * k + 2;
                    if (interior || (j0 + m0 + c < NP1)) {
                        float Sp = DBP + fp.y, St = DBT + ft.y;
                        float df = fabsf(__log2f(Sp + EPSW) - __log2f(St + EPSW));
                        s1 += df; s2 += df * St; mx = fmaxf(mx, St);
                    }
                }
            }
        }

        // ---- Block reduction of (S1, S2, M) ----
        #pragma unroll
        for (int off = 16; off > 0; off >>= 1) {
            s1 += __shfl_down_sync(0xffffffffu, s1, off);
            s2 += __shfl_down_sync(0xffffffffu, s2, off);
            mx  = fmaxf(mx, __shfl_down_sync(0xffffffffu, mx, off));
        }
        if (lane == 0) { sm.red1[wid] = s1; sm.red2[wid] = s2; sm.red3[wid] = mx; }
        __syncthreads();   // all env/base/h2 reads done -> next iter may overwrite

        if (t == 0) {
            float a1 = 0.f, a2 = 0.f, am = 0.f;
            #pragma unroll
            for (int w = 0; w < 8; w++) {
                a1 += sm.red1[w]; a2 += sm.red2[w]; am = fmaxf(am, sm.red3[w]);
            }
            atomicAdd(&g_acc[row].s1, (double)a1 * LN2);   // log2 -> ln
            atomicAdd(&g_acc[row].s2, (double)a2 * LN2);
            atomicMax(&g_acc[row].m, __float_as_int(am));  // raw max, >= 0
        }
        tau = ntau;
    }

    // ---- Completion count + finalize (once per block) ----
    if (t == 0) {
        __threadfence();
        unsigned int old = atomicAdd(&g_count, 1u);
        sm.flag = (old == (unsigned)GRID - 1u) ? 1 : 0;
    }
    __syncthreads();

    if (sm.flag) {
        __threadfence();
        if (t < B) {
            volatile double* p1 = &g_acc[t].s1;
            volatile double* p2 = &g_acc[t].s2;
            volatile int*    pm = &g_acc[t].m;
            double S1 = *p1;                   // sum df            (true scale)
            double S2 = *p2;                   // sum df * S_t      (240x scale)
            float  M  = __int_as_float(*pm);   // 240 * true max
            sm.fin[t] = 0.2 * S1 + 0.8 * S2 / ((double)M + (double)EPSW);
            g_acc[t].s1 = 0.0; g_acc[t].s2 = 0.0; g_acc[t].m = 0;
        }
        __syncthreads();
        if (t == 0) {
            double tot = 0.0;
            for (int r = 0; r < B; r++) tot += sm.fin[r];
            out[0] = (float)(tot * invcnt);
            g_count = 0u;
            __threadfence();
        }
    }
}

extern "C" void kernel_launch(void* const* d_in, const int* in_sizes, int n_in,
                              void* d_out, int out_size)
{
    const float* y_pred = (const float*)d_in[0];
    const float* y_true = (const float*)d_in[1];
    float* out = (float*)d_out;

    const int B       = in_sizes[0] / N_SAMP;            // 16
    const int n_tiles = TILES_X * B;                     // 2016

    k_fused<<<GRID, NTHR>>>(y_pred, y_true, out, B, n_tiles,
                            1.0 / ((double)B * (double)NP1));
}

// round 17
// speedup vs baseline: 1.1388x; 1.1388x over previous
#include <cuda_runtime.h>
#include <cuda_fp16.h>
#include <cstdint>

// Problem constants (16 clips of 10 s @ 48 kHz)
#define N_SAMP  480000
#define NP1     480001          // envelope length per row
#define WIN     240             // 5 ms box filter
#define EPSW    (240.0f * 1e-6f)   // eps on raw window sums
#define LN2     0.6931471805599453

// Tiling: 256 threads, 16 d-elements each; window offset 240 = 15 thread slots.
#define NTHR    256
#define EPT     16
#define T_OUT   3840            // envelope outputs per block (threads 0..239 x 16)
#define L_DV    (T_OUT + WIN - 1)   // 4079 valid d elements per tile
#define TILES_X 126
#define MAXB    16

// Scratch (zero-initialized at load; reset by last block each run)
struct RowAcc { double s1, s2; int m; int pad[3]; };
__device__ RowAcc       g_acc[MAXB];
__device__ unsigned int g_count;

struct SMF {
    float   baseP[NTHR], baseT[NTHR];   // per-thread exclusive prefix bases
    __half2 h2P[NTHR * 9];              // local inclusive prefixes, idx 9t+k (CF)
    __half2 h2T[NTHR * 9];
    float   wsP[8], wsT[8];
    float   red1[8], red2[8], red3[8];
    double  fin[MAXB];
    int     flag;
};

// One signal: load 17 x-values, compute local inclusive |diff| prefixes,
// pack to smem as produced (staging regs die fast), warp-scan the total.
// Returns (s = thread total, v = warp-inclusive total).
template<bool INTERIOR>
__device__ __forceinline__ void pass_one(const float* __restrict__ x,
                                         int j0, int m0, int lane,
                                         __half2* __restrict__ rp,
                                         float& s, float& v)
{
    s = 0.f;
    if (INTERIOR) {
        float h = 0.f;
        if (lane == 0) h = x[j0 - 121 + m0];
        const float4* p4 = reinterpret_cast<const float4*>(x + (j0 - 120 + m0));
        float4 A0 = p4[0], A1 = p4[1], A2 = p4[2], A3 = p4[3];
        float e[EPT] = { A0.x, A0.y, A0.z, A0.w,  A1.x, A1.y, A1.z, A1.w,
                         A2.x, A2.y, A2.z, A2.w,  A3.x, A3.y, A3.z, A3.w };
        float prev = __shfl_up_sync(0xffffffffu, A3.w, 1);
        if (lane == 0) prev = h;
        #pragma unroll
        for (int k = 0; k < 8; k++) {
            float a = s + fabsf(e[2*k]   - prev);
            float b = a + fabsf(e[2*k+1] - e[2*k]);
            rp[k] = __floats2half2_rn(a, b);
            prev = e[2*k+1]; s = b;
        }
    } else {
        float prev;
        {
            int i = j0 - 121 + m0;
            prev = (i >= 0 && i < N_SAMP) ? x[i] : 0.f;
        }
        #pragma unroll
        for (int k = 0; k < 8; k++) {
            float ab[2];
            #pragma unroll
            for (int hh = 0; hh < 2; hh++) {
                int c = 2*k + hh;
                int i = j0 - 120 + m0 + c;       // x index == d index
                bool vv = (i >= 0) && (i < N_SAMP);
                float cur = vv ? x[i] : 0.f;
                bool ok = (i >= 1) && (i < N_SAMP) && (m0 + c < L_DV);
                s += ok ? fabsf(cur - prev) : 0.f;
                prev = cur;
                ab[hh] = s;
            }
            rp[k] = __floats2half2_rn(ab[0], ab[1]);
        }
    }
    // warp inclusive scan of thread totals
    v = s;
    #pragma unroll
    for (int off = 1; off < 32; off <<= 1) {
        float u = __shfl_up_sync(0xffffffffu, v, off);
        if (lane >= off) v += u;
    }
}

__global__ __launch_bounds__(NTHR, 6)
void k_fused(const float* __restrict__ y_pred, const float* __restrict__ y_true,
             float* __restrict__ out, int B, double invcnt)
{
    __shared__ SMF sm;
    const int t = threadIdx.x, lane = t & 31, wid = t >> 5;
    const int row = blockIdx.y;
    const int j0  = blockIdx.x * T_OUT;
    const int m0  = t * EPT;
    const float* xp = y_pred + (size_t)row * N_SAMP;
    const float* xt = y_true + (size_t)row * N_SAMP;

    const bool interior = (blockIdx.x >= 1) && (blockIdx.x + 2 < gridDim.x);

    // ---- Signal-sequential diffs+pack+scan (low register peak) ----
    float sP, vP, sT, vT;
    if (interior) {
        pass_one<true >(xp, j0, m0, lane, &sm.h2P[9 * t], sP, vP);
        pass_one<true >(xt, j0, m0, lane, &sm.h2T[9 * t], sT, vT);
    } else {
        pass_one<false>(xp, j0, m0, lane, &sm.h2P[9 * t], sP, vP);
        pass_one<false>(xt, j0, m0, lane, &sm.h2T[9 * t], sT, vT);
    }
    if (lane == 31) { sm.wsP[wid] = vP; sm.wsT[wid] = vT; }
    __syncthreads();

    float baseP = vP - sP, baseT = vT - sT;
    #pragma unroll
    for (int w = 0; w < 7; w++)
        if (w < wid) { baseP += sm.wsP[w]; baseT += sm.wsT[w]; }
    sm.baseP[t] = baseP;
    sm.baseT[t] = baseT;
    __syncthreads();

    // ---- Env + loss on the fly: S = (bN-bO) + (runN-runO) ----
    float s1 = 0.f, s2 = 0.f, mx = 0.f;
    if (t < T_OUT / EPT) {                       // t < 240
        const float DBP = sm.baseP[t + 15] - baseP;
        const float DBT = sm.baseT[t + 15] - baseT;
        const __half2* qp = &sm.h2P[9 * (t + 15)];
        const __half2* op = &sm.h2P[9 * t];
        const __half2* qt = &sm.h2T[9 * (t + 15)];
        const __half2* ot = &sm.h2T[9 * t];
        if (interior || (j0 + m0 < NP1)) {       // c = 0
            float df = fabsf(__log2f(DBP + EPSW) - __log2f(DBT + EPSW));
            s1 += df; s2 += df * DBT; mx = fmaxf(mx, DBT);
        }
        #pragma unroll
        for (int k = 0; k < 8; k++) {
            float2 fp = __half22float2(__hsub2(qp[k], op[k]));
            float2 ft = __half22float2(__hsub2(qt[k], ot[k]));
            {
                int c = 2 * k + 1;
                if (interior || (j0 + m0 + c < NP1)) {
                    float Sp = DBP + fp.x, St = DBT + ft.x;
                    float df = fabsf(__log2f(Sp + EPSW) - __log2f(St + EPSW));
                    s1 += df; s2 += df * St; mx = fmaxf(mx, St);
                }
            }
            if (k < 7) {
                int c = 2 * k + 2;
                if (interior || (j0 + m0 + c < NP1)) {
                    float Sp = DBP + fp.y, St = DBT + ft.y;
                    float df = fabsf(__log2f(Sp + EPSW) - __log2f(St + EPSW));
                    s1 += df; s2 += df * St; mx = fmaxf(mx, St);
                }
            }
        }
    }

    // ---- Block reduction of (S1, S2, M) ----
    #pragma unroll
    for (int off = 16; off > 0; off >>= 1) {
        s1 += __shfl_down_sync(0xffffffffu, s1, off);
        s2 += __shfl_down_sync(0xffffffffu, s2, off);
        mx  = fmaxf(mx, __shfl_down_sync(0xffffffffu, mx, off));
    }
    if (lane == 0) { sm.red1[wid] = s1; sm.red2[wid] = s2; sm.red3[wid] = mx; }
    __syncthreads();

    if (t == 0) {
        float a1 = 0.f, a2 = 0.f, am = 0.f;
        #pragma unroll
        for (int w = 0; w < 8; w++) {
            a1 += sm.red1[w]; a2 += sm.red2[w]; am = fmaxf(am, sm.red3[w]);
        }
        atomicAdd(&g_acc[row].s1, (double)a1 * LN2);   // log2 -> ln
        atomicAdd(&g_acc[row].s2, (double)a2 * LN2);
        atomicMax(&g_acc[row].m, __float_as_int(am));  // raw window-sum max, >= 0
        __threadfence();

        unsigned int total = gridDim.x * gridDim.y;
        unsigned int old = atomicAdd(&g_count, 1u);
        sm.flag = (old == total - 1u) ? 1 : 0;
    }
    __syncthreads();

    if (sm.flag) {
        // Last block: finalize in parallel, reset scratch for next replay.
        __threadfence();
        if (t < B) {
            volatile double* p1 = &g_acc[t].s1;
            volatile double* p2 = &g_acc[t].s2;
            volatile int*    pm = &g_acc[t].m;
            double S1 = *p1;                   // sum df            (true scale)
            double S2 = *p2;                   // sum df * S_t      (240x scale)
            float  M  = __int_as_float(*pm);   // 240 * true max
            sm.fin[t] = 0.2 * S1 + 0.8 * S2 / ((double)M + (double)EPSW);
            g_acc[t].s1 = 0.0; g_acc[t].s2 = 0.0; g_acc[t].m = 0;
        }
        __syncthreads();
        if (t == 0) {
            double tot = 0.0;
            for (int r = 0; r < B; r++) tot += sm.fin[r];
            out[0] = (float)(tot * invcnt);
            g_count = 0u;
            __threadfence();
        }
    }
}

extern "C" void kernel_launch(void* const* d_in, const int* in_sizes, int n_in,
                              void* d_out, int out_size)
{
    const float* y_pred = (const float*)d_in[0];
    const float* y_true = (const float*)d_in[1];
    float* out = (float*)d_out;

    const int B     = in_sizes[0] / N_SAMP;              // 16
    const int tiles = (NP1 + T_OUT - 1) / T_OUT;         // 126

    k_fused<<<dim3(tiles, B), NTHR>>>(y_pred, y_true, out, B,
                                      1.0 / ((double)B * (double)NP1));
}